// round 1
// baseline (speedup 1.0000x reference)
#include <cuda_runtime.h>
#include <cuda_bf16.h>
#include <math.h>

// ---------------------------------------------------------------------------
// Multi-Latent Attention — fp32 baseline
// B=2 S=2048 D=2048 H=16 HKV=4 RQ=1024 RKV=512 DH=192 DR=64 DN=128 DV=128
// ---------------------------------------------------------------------------

#define Bsz   2
#define SEQ   2048
#define DMODEL 2048
#define NH    16
#define NKV   4
#define RQ_   1024
#define RKV_  512
#define DH_   192
#define DR_   64
#define DN_   128
#define DV_   128
#define ROWS  (Bsz*SEQ)          // 4096

// ----------------------------- scratch ------------------------------------
__device__ float g_qa [ROWS * RQ_];            // 4096x1024
__device__ float g_qb [ROWS * (NH*DH_)];       // 4096x3072
__device__ float g_kva[ROWS * (RKV_ + DR_)];   // 4096x576
__device__ float g_kvb[ROWS * (NKV*(DN_+DV_))];// 4096x1024
__device__ float g_Q  [Bsz*NH *SEQ*DH_];       // 12.6M
__device__ float g_K  [Bsz*NKV*SEQ*DH_];       // 3.1M
__device__ float g_V  [Bsz*NKV*SEQ*DV_];       // 2.1M
__device__ float g_attn[ROWS * (NH*DV_)];      // 4096x2048

// ----------------------------- SGEMM + bias --------------------------------
// C[M,N] = A[M,K(lda)] * B[K,N(ldb)] + bias[N].  Row-major everywhere.
// BM=128 BN=64 BK=16, 256 threads, thread tile 8x4.
// Requires: M%128==0, N%64==0, K%16==0, lda/ldb/ldc %4==0 (all true here).
#define GBM 128
#define GBN 64
#define GBK 16

__global__ __launch_bounds__(256)
void sgemm_bias(int M, int N, int K,
                const float* __restrict__ A, int lda,
                const float* __restrict__ B, int ldb,
                const float* __restrict__ bias,
                float* __restrict__ C, int ldc)
{
    __shared__ float As[GBK][GBM];
    __shared__ float Bs[GBK][GBN];

    const int tid = threadIdx.x;
    const int bm0 = blockIdx.y * GBM;
    const int bn0 = blockIdx.x * GBN;
    const int tx = tid & 15;       // n dir
    const int ty = tid >> 4;       // m dir

    float acc[8][4];
    #pragma unroll
    for (int i = 0; i < 8; i++)
        #pragma unroll
        for (int j = 0; j < 4; j++) acc[i][j] = 0.f;

    for (int k0 = 0; k0 < K; k0 += GBK) {
        // load A tile (128x16) transposed into As[k][m]
        #pragma unroll
        for (int it = 0; it < 2; it++) {
            int idx = tid + it * 256;          // 0..511
            int row = idx >> 2;                // 0..127
            int k4  = (idx & 3) * 4;
            float4 a = *reinterpret_cast<const float4*>(
                &A[(size_t)(bm0 + row) * lda + k0 + k4]);
            As[k4+0][row] = a.x; As[k4+1][row] = a.y;
            As[k4+2][row] = a.z; As[k4+3][row] = a.w;
        }
        // load B tile (16x64)
        {
            int row = tid >> 4;                // k 0..15
            int n4  = (tid & 15) * 4;
            *reinterpret_cast<float4*>(&Bs[row][n4]) =
                *reinterpret_cast<const float4*>(
                    &B[(size_t)(k0 + row) * ldb + bn0 + n4]);
        }
        __syncthreads();

        #pragma unroll
        for (int k = 0; k < GBK; k++) {
            float4 a0 = *reinterpret_cast<float4*>(&As[k][ty*8]);
            float4 a1 = *reinterpret_cast<float4*>(&As[k][ty*8+4]);
            float4 bv = *reinterpret_cast<float4*>(&Bs[k][tx*4]);
            float a[8] = {a0.x,a0.y,a0.z,a0.w,a1.x,a1.y,a1.z,a1.w};
            float b[4] = {bv.x,bv.y,bv.z,bv.w};
            #pragma unroll
            for (int i = 0; i < 8; i++)
                #pragma unroll
                for (int j = 0; j < 4; j++)
                    acc[i][j] = fmaf(a[i], b[j], acc[i][j]);
        }
        __syncthreads();
    }

    float bb[4];
    #pragma unroll
    for (int j = 0; j < 4; j++) bb[j] = bias[bn0 + tx*4 + j];
    #pragma unroll
    for (int i = 0; i < 8; i++) {
        float4 o;
        o.x = acc[i][0] + bb[0];
        o.y = acc[i][1] + bb[1];
        o.z = acc[i][2] + bb[2];
        o.w = acc[i][3] + bb[3];
        *reinterpret_cast<float4*>(
            &C[(size_t)(bm0 + ty*8 + i) * ldc + bn0 + tx*4]) = o;
    }
}

// ----------------------------- rmsnorm (in place) ---------------------------
__global__ __launch_bounds__(256)
void rmsnorm_kernel(float* __restrict__ x, const float* __restrict__ g,
                    int W, int stride)
{
    __shared__ float warp_s[8];
    int row = blockIdx.x;
    float* xr = x + (size_t)row * stride;

    float ss = 0.f;
    for (int j = threadIdx.x; j < W; j += 256) { float v = xr[j]; ss = fmaf(v, v, ss); }
    #pragma unroll
    for (int o = 16; o; o >>= 1) ss += __shfl_xor_sync(0xffffffffu, ss, o);
    if ((threadIdx.x & 31) == 0) warp_s[threadIdx.x >> 5] = ss;
    __syncthreads();
    if (threadIdx.x < 8) {
        float v = warp_s[threadIdx.x];
        #pragma unroll
        for (int o = 4; o; o >>= 1) v += __shfl_xor_sync(0xffu, v, o);
        if (threadIdx.x == 0) warp_s[0] = v;
    }
    __syncthreads();
    float inv = rsqrtf(warp_s[0] / (float)W + 1e-20f);
    for (int j = threadIdx.x; j < W; j += 256) xr[j] = xr[j] * inv * g[j];
}

// ----------------------------- RoPE helpers --------------------------------
__device__ __forceinline__ float2 rope_cs(int s, int idx)
{
    float t = (float)(2 * idx) / 64.0f;
    float inv_freq = 1.0f / powf(10000.0f, t);
    float ang = (float)s * inv_freq;
    return make_float2(cosf(ang), sinf(ang));
}

// q_b [4096, H*192] -> Q [B,H,S,192] with per-head layout [rope(64) | nrope(128)]
__global__ __launch_bounds__(256)
void rope_q_kernel(const float* __restrict__ qb, float* __restrict__ Q)
{
    int t = blockIdx.x * 256 + threadIdx.x;
    const int TOTAL = Bsz * NH * SEQ * DH_;
    if (t >= TOTAL) return;
    int j = t % DH_;
    int s = (t / DH_) % SEQ;
    int h = (t / (DH_ * SEQ)) % NH;
    int b = t / (DH_ * SEQ * NH);
    size_t src = ((size_t)(b * SEQ + s)) * (NH * DH_) + h * DH_;
    float val;
    if (j >= DR_) {
        val = qb[src + (j - DR_)];                   // nrope
    } else {
        float x   = qb[src + DN_ + j];
        float rot = (j < 32) ? -qb[src + DN_ + j + 32] : qb[src + DN_ + j - 32];
        int idx = (j < 32) ? j : j - 32;
        float2 cs = rope_cs(s, idx);
        val = x * cs.x + rot * cs.y;
    }
    Q[t] = val;
}

// kv_a [4096,576] (rope cols 512..575), kv_b [4096, 4*256]
// -> K [B,HKV,S,192] ([rope|nrope]), V [B,HKV,S,128]
__global__ __launch_bounds__(256)
void build_kv_kernel(const float* __restrict__ kva, const float* __restrict__ kvb,
                     float* __restrict__ K, float* __restrict__ V)
{
    int t = blockIdx.x * 256 + threadIdx.x;
    const int PER = DH_ + DV_;                       // 320
    const int TOTAL = Bsz * NKV * SEQ * PER;
    if (t >= TOTAL) return;
    int j = t % PER;
    int s = (t / PER) % SEQ;
    int g = (t / (PER * SEQ)) % NKV;
    int b = t / (PER * SEQ * NKV);
    size_t rowa = ((size_t)(b * SEQ + s)) * (RKV_ + DR_);
    size_t rowb = ((size_t)(b * SEQ + s)) * (NKV * (DN_ + DV_)) + g * (DN_ + DV_);
    if (j < DH_) {
        float val;
        if (j < DR_) {
            float x   = kva[rowa + RKV_ + j];
            float rot = (j < 32) ? -kva[rowa + RKV_ + j + 32] : kva[rowa + RKV_ + j - 32];
            int idx = (j < 32) ? j : j - 32;
            float2 cs = rope_cs(s, idx);
            val = x * cs.x + rot * cs.y;
        } else {
            val = kvb[rowb + (j - DR_)];
        }
        K[(((size_t)(b * NKV + g)) * SEQ + s) * DH_ + j] = val;
    } else {
        V[(((size_t)(b * NKV + g)) * SEQ + s) * DV_ + (j - DH_)] =
            kvb[rowb + DN_ + (j - DH_)];
    }
}

// ----------------------------- flash attention (fp32) ----------------------
// Per block: 64 q-rows of one (b,h). Online softmax over causal K tiles of 32.
#define AQ 64
#define AK 32
#define KS_STRIDE 36     // padded K^T row stride (floats)
#define PS_STRIDE 68     // padded P^T row stride (floats)

#define SM_QS    0                              // [64][192]
#define SM_KS    (SM_QS + AQ*DH_)               // [192][36]
#define SM_VS    (SM_KS + DH_*KS_STRIDE)        // [32][128]
#define SM_SS    (SM_VS + AK*DV_)               // [64][33]
#define SM_PS    (SM_SS + AQ*33)                // [32][68]
#define SM_M     (SM_PS + AK*PS_STRIDE)
#define SM_L     (SM_M + AQ)
#define SM_AL    (SM_L + AQ)
#define SM_TOTAL (SM_AL + AQ)                   // floats
#define ATTN_SMEM_BYTES (SM_TOTAL * 4)

__global__ __launch_bounds__(256)
void attn_kernel(const float* __restrict__ Q, const float* __restrict__ K,
                 const float* __restrict__ V, float* __restrict__ Out)
{
    extern __shared__ float sm[];
    float* Qs = sm + SM_QS;
    float* Ks = sm + SM_KS;
    float* Vs = sm + SM_VS;
    float* Ss = sm + SM_SS;
    float* Ps = sm + SM_PS;
    float* m_s  = sm + SM_M;
    float* l_s  = sm + SM_L;
    float* al_s = sm + SM_AL;

    const int tid = threadIdx.x;
    const int q0 = blockIdx.x * AQ;
    const int h  = blockIdx.y;
    const int b  = blockIdx.z;
    const int g  = h >> 2;                       // GROUPS = 4
    const float scale = 1.0f / sqrtf((float)DH_);

    const float* Qg = Q + (((size_t)(b * NH + h)) * SEQ + q0) * DH_;
    const float* Kg = K + ((size_t)(b * NKV + g)) * SEQ * DH_;
    const float* Vg = V + ((size_t)(b * NKV + g)) * SEQ * DV_;

    // load Q tile (contiguous 64*192 floats)
    for (int idx = tid; idx < AQ * DH_ / 4; idx += 256)
        reinterpret_cast<float4*>(Qs)[idx] =
            reinterpret_cast<const float4*>(Qg)[idx];
    if (tid < AQ) { m_s[tid] = -INFINITY; l_s[tid] = 0.f; }

    const int ty = tid >> 4;     // 0..15 : O rows ty*4..+3, S rows ty*4..+3
    const int tx = tid & 15;     // O cols tx*8..+7, S cols tx*2..+1

    float o[4][8];
    #pragma unroll
    for (int i = 0; i < 4; i++)
        #pragma unroll
        for (int j = 0; j < 8; j++) o[i][j] = 0.f;

    const int kend = q0 + AQ;    // causal
    for (int ks = 0; ks < kend; ks += AK) {
        __syncthreads();
        // K tile -> transposed Ks[d][c]
        for (int idx = tid; idx < AK * (DH_ / 4); idx += 256) {
            int c  = idx / (DH_ / 4);
            int d4 = idx % (DH_ / 4);
            float4 kv = reinterpret_cast<const float4*>(
                Kg + (size_t)(ks + c) * DH_)[d4];
            Ks[(d4*4+0)*KS_STRIDE + c] = kv.x;
            Ks[(d4*4+1)*KS_STRIDE + c] = kv.y;
            Ks[(d4*4+2)*KS_STRIDE + c] = kv.z;
            Ks[(d4*4+3)*KS_STRIDE + c] = kv.w;
        }
        // V tile (contiguous)
        for (int idx = tid; idx < AK * DV_ / 4; idx += 256)
            reinterpret_cast<float4*>(Vs)[idx] =
                reinterpret_cast<const float4*>(Vg + (size_t)ks * DV_)[idx];
        __syncthreads();

        // scores: thread computes 4 rows x 2 cols over d=192
        float sc[4][2];
        #pragma unroll
        for (int i = 0; i < 4; i++) { sc[i][0] = 0.f; sc[i][1] = 0.f; }
        #pragma unroll 4
        for (int d = 0; d < DH_; d++) {
            float2 kvv = *reinterpret_cast<float2*>(&Ks[d*KS_STRIDE + tx*2]);
            #pragma unroll
            for (int i = 0; i < 4; i++) {
                float qv = Qs[(ty*4+i)*DH_ + d];
                sc[i][0] = fmaf(qv, kvv.x, sc[i][0]);
                sc[i][1] = fmaf(qv, kvv.y, sc[i][1]);
            }
        }
        #pragma unroll
        for (int i = 0; i < 4; i++) {
            Ss[(ty*4+i)*33 + tx*2 + 0] = sc[i][0];
            Ss[(ty*4+i)*33 + tx*2 + 1] = sc[i][1];
        }
        __syncthreads();

        // softmax: 4 threads per row (r = tid>>2, quad = tid&3)
        {
            int r  = tid >> 2;
            int qd = tid & 3;
            float m_old = m_s[r];
            float mx = m_old;
            #pragma unroll 8
            for (int c = 0; c < AK; c++) {
                float sv = (ks + c <= q0 + r) ? Ss[r*33 + c] * scale : -INFINITY;
                mx = fmaxf(mx, sv);
            }
            float alpha = expf(m_old - mx);
            float lsum = 0.f;
            #pragma unroll
            for (int c = qd * 8; c < qd * 8 + 8; c++) {
                float sv = (ks + c <= q0 + r) ? Ss[r*33 + c] * scale : -INFINITY;
                float p = expf(sv - mx);
                Ps[c*PS_STRIDE + r] = p;
                lsum += p;
            }
            lsum += __shfl_xor_sync(0xffffffffu, lsum, 1);
            lsum += __shfl_xor_sync(0xffffffffu, lsum, 2);
            if (qd == 0) {
                m_s[r]  = mx;
                l_s[r]  = l_s[r] * alpha + lsum;
                al_s[r] = alpha;
            }
        }
        __syncthreads();

        // O update: rescale then accumulate P@V (4 rows x 8 dv per thread)
        {
            #pragma unroll
            for (int i = 0; i < 4; i++) {
                float al = al_s[ty*4 + i];
                #pragma unroll
                for (int j = 0; j < 8; j++) o[i][j] *= al;
            }
            #pragma unroll 4
            for (int c = 0; c < AK; c++) {
                float4 p4 = *reinterpret_cast<float4*>(&Ps[c*PS_STRIDE + ty*4]);
                float pv[4] = {p4.x, p4.y, p4.z, p4.w};
                float4 v0 = *reinterpret_cast<float4*>(&Vs[c*DV_ + tx*8]);
                float4 v1 = *reinterpret_cast<float4*>(&Vs[c*DV_ + tx*8 + 4]);
                float vv[8] = {v0.x,v0.y,v0.z,v0.w,v1.x,v1.y,v1.z,v1.w};
                #pragma unroll
                for (int i = 0; i < 4; i++)
                    #pragma unroll
                    for (int j = 0; j < 8; j++)
                        o[i][j] = fmaf(pv[i], vv[j], o[i][j]);
            }
        }
    }

    // write out: [B,S,H*DV]
    #pragma unroll
    for (int i = 0; i < 4; i++) {
        int r = ty*4 + i;
        float invl = 1.0f / l_s[r];
        size_t orow = ((size_t)(b * SEQ + q0 + r)) * (NH * DV_) + h * DV_ + tx*8;
        float4 w0, w1;
        w0.x = o[i][0]*invl; w0.y = o[i][1]*invl; w0.z = o[i][2]*invl; w0.w = o[i][3]*invl;
        w1.x = o[i][4]*invl; w1.y = o[i][5]*invl; w1.z = o[i][6]*invl; w1.w = o[i][7]*invl;
        *reinterpret_cast<float4*>(&Out[orow])     = w0;
        *reinterpret_cast<float4*>(&Out[orow + 4]) = w1;
    }
}

// ----------------------------- host ----------------------------------------
extern "C" void kernel_launch(void* const* d_in, const int* in_sizes, int n_in,
                              void* d_out, int out_size)
{
    const float* X     = (const float*)d_in[0];
    // d_in[1] = attention_mask (causal tril) — structure is known, unused
    const float* w_qa  = (const float*)d_in[2];
    const float* b_qa  = (const float*)d_in[3];
    const float* gq    = (const float*)d_in[4];
    const float* w_qb  = (const float*)d_in[5];
    const float* b_qb  = (const float*)d_in[6];
    const float* w_kva = (const float*)d_in[7];
    const float* b_kva = (const float*)d_in[8];
    const float* gkv   = (const float*)d_in[9];
    const float* w_kvb = (const float*)d_in[10];
    const float* b_kvb = (const float*)d_in[11];
    const float* w_o   = (const float*)d_in[12];
    const float* b_o   = (const float*)d_in[13];
    float* out = (float*)d_out;

    float *qa, *qb, *kva, *kvb, *Q, *K, *V, *attn;
    cudaGetSymbolAddress((void**)&qa,  g_qa);
    cudaGetSymbolAddress((void**)&qb,  g_qb);
    cudaGetSymbolAddress((void**)&kva, g_kva);
    cudaGetSymbolAddress((void**)&kvb, g_kvb);
    cudaGetSymbolAddress((void**)&Q,   g_Q);
    cudaGetSymbolAddress((void**)&K,   g_K);
    cudaGetSymbolAddress((void**)&V,   g_V);
    cudaGetSymbolAddress((void**)&attn,g_attn);

    // q path
    sgemm_bias<<<dim3(RQ_/GBN, ROWS/GBM), 256>>>(ROWS, RQ_, DMODEL,
        X, DMODEL, w_qa, RQ_, b_qa, qa, RQ_);
    rmsnorm_kernel<<<ROWS, 256>>>(qa, gq, RQ_, RQ_);
    sgemm_bias<<<dim3((NH*DH_)/GBN, ROWS/GBM), 256>>>(ROWS, NH*DH_, RQ_,
        qa, RQ_, w_qb, NH*DH_, b_qb, qb, NH*DH_);

    // kv path
    sgemm_bias<<<dim3((RKV_+DR_)/GBN, ROWS/GBM), 256>>>(ROWS, RKV_+DR_, DMODEL,
        X, DMODEL, w_kva, RKV_+DR_, b_kva, kva, RKV_+DR_);
    rmsnorm_kernel<<<ROWS, 256>>>(kva, gkv, RKV_, RKV_+DR_);
    sgemm_bias<<<dim3((NKV*(DN_+DV_))/GBN, ROWS/GBM), 256>>>(ROWS, NKV*(DN_+DV_), RKV_,
        kva, RKV_+DR_, w_kvb, NKV*(DN_+DV_), b_kvb, kvb, NKV*(DN_+DV_));

    // rope + layout
    {
        int n1 = Bsz*NH*SEQ*DH_;
        rope_q_kernel<<<(n1 + 255)/256, 256>>>(qb, Q);
        int n2 = Bsz*NKV*SEQ*(DH_+DV_);
        build_kv_kernel<<<(n2 + 255)/256, 256>>>(kva, kvb, K, V);
    }

    // attention
    cudaFuncSetAttribute(attn_kernel,
        cudaFuncAttributeMaxDynamicSharedMemorySize, ATTN_SMEM_BYTES);
    attn_kernel<<<dim3(SEQ/AQ, NH, Bsz), 256, ATTN_SMEM_BYTES>>>(Q, K, V, attn);

    // out projection
    sgemm_bias<<<dim3(DMODEL/GBN, ROWS/GBM), 256>>>(ROWS, DMODEL, NH*DV_,
        attn, NH*DV_, w_o, DMODEL, b_o, out, DMODEL);
}

// round 3
// speedup vs baseline: 1.3987x; 1.3987x over previous
#include <cuda_runtime.h>
#include <cuda_bf16.h>
#include <math.h>
#include <stdint.h>

// ---------------------------------------------------------------------------
// Multi-Latent Attention — mma.sync bf16x3 GEMMs + fp32 flash attention
// B=2 S=2048 D=2048 H=16 HKV=4 RQ=1024 RKV=512 DH=192 DR=64 DN=128 DV=128
// ---------------------------------------------------------------------------

#define Bsz   2
#define SEQ   2048
#define DMODEL 2048
#define NH    16
#define NKV   4
#define RQ_   1024
#define RKV_  512
#define DH_   192
#define DR_   64
#define DN_   128
#define DV_   128
#define ROWS  (Bsz*SEQ)          // 4096
#define KVAPAD 640               // kv_a N padded 576 -> 640

// ----------------------------- scratch (fp32) ------------------------------
__device__ float g_qa [ROWS * RQ_];
__device__ float g_qb [ROWS * (NH*DH_)];
__device__ float g_kva[ROWS * KVAPAD];
__device__ float g_kvb[ROWS * (NKV*(DN_+DV_))];
__device__ float g_Q  [Bsz*NH *SEQ*DH_];
__device__ float g_K  [Bsz*NKV*SEQ*DH_];
__device__ float g_V  [Bsz*NKV*SEQ*DV_];
__device__ float g_attn[ROWS * (NH*DV_)];

// ----------------------------- scratch (bf16 splits) ------------------------
__device__ __nv_bfloat16 g_Xhi [ROWS*DMODEL];
__device__ __nv_bfloat16 g_Xlo [ROWS*DMODEL];
__device__ __nv_bfloat16 g_QAhi[ROWS*RQ_];
__device__ __nv_bfloat16 g_QAlo[ROWS*RQ_];
__device__ __nv_bfloat16 g_KVAhi[ROWS*RKV_];
__device__ __nv_bfloat16 g_KVAlo[ROWS*RKV_];
__device__ __nv_bfloat16 g_AThi[ROWS*(NH*DV_)];
__device__ __nv_bfloat16 g_ATlo[ROWS*(NH*DV_)];
// transposed weights [N][K] bf16 hi/lo
__device__ __nv_bfloat16 g_Wqa_hi [RQ_ * DMODEL];
__device__ __nv_bfloat16 g_Wqa_lo [RQ_ * DMODEL];
__device__ __nv_bfloat16 g_Wqb_hi [(NH*DH_) * RQ_];
__device__ __nv_bfloat16 g_Wqb_lo [(NH*DH_) * RQ_];
__device__ __nv_bfloat16 g_Wkva_hi[KVAPAD * DMODEL];
__device__ __nv_bfloat16 g_Wkva_lo[KVAPAD * DMODEL];
__device__ __nv_bfloat16 g_Wkvb_hi[(NKV*(DN_+DV_)) * RKV_];
__device__ __nv_bfloat16 g_Wkvb_lo[(NKV*(DN_+DV_)) * RKV_];
__device__ __nv_bfloat16 g_Wo_hi  [DMODEL * (NH*DV_)];
__device__ __nv_bfloat16 g_Wo_lo  [DMODEL * (NH*DV_)];

// ----------------------------- PTX helpers ---------------------------------
__device__ __forceinline__ uint32_t smem_u32(const void* p) {
    uint32_t a;
    asm("{ .reg .u64 t; cvta.to.shared.u64 t, %1; cvt.u32.u64 %0, t; }"
        : "=r"(a) : "l"(p));
    return a;
}
__device__ __forceinline__ void cp16(uint32_t dst, const void* src) {
    asm volatile("cp.async.cg.shared.global [%0], [%1], 16;"
                 :: "r"(dst), "l"(src) : "memory");
}
#define CP_COMMIT() asm volatile("cp.async.commit_group;" ::: "memory")
#define CP_WAIT(n)  asm volatile("cp.async.wait_group %0;" :: "n"(n) : "memory")

__device__ __forceinline__ void ldsm_x4(uint32_t* r, uint32_t addr) {
    asm volatile("ldmatrix.sync.aligned.m8n8.x4.shared.b16 {%0,%1,%2,%3}, [%4];"
                 : "=r"(r[0]), "=r"(r[1]), "=r"(r[2]), "=r"(r[3]) : "r"(addr));
}
__device__ __forceinline__ void mma16816(float* c, const uint32_t* a,
                                         uint32_t b0, uint32_t b1) {
    asm volatile(
        "mma.sync.aligned.m16n8k16.row.col.f32.bf16.bf16.f32 "
        "{%0,%1,%2,%3}, {%4,%5,%6,%7}, {%8,%9}, {%0,%1,%2,%3};"
        : "+f"(c[0]), "+f"(c[1]), "+f"(c[2]), "+f"(c[3])
        : "r"(a[0]), "r"(a[1]), "r"(a[2]), "r"(a[3]), "r"(b0), "r"(b1));
}

// ----------------------------- tc GEMM (mma.sync bf16x3) --------------------
// C[M,N] = (Ahi+Alo)[M,K] @ (Bhi+Blo)[N,K]^T + bias[N], fp32 out.
// Tile 128x128x32, 256 threads (8 warps, 4x2), double-buffered cp.async.
#define BK    32
#define RSTR  40                       // halves per smem row (80B: conflict-free ldmatrix)
#define TILE_H (128*RSTR)              // 5120 halves per matrix tile
#define STAGE_H (4*TILE_H)             // Ah, Al, Bh, Bl
#define TC_SMEM_BYTES (2*STAGE_H*2)    // 81920 bytes

__global__ __launch_bounds__(256)
void tc_gemm_bias(int M, int N, int K,
                  const __nv_bfloat16* __restrict__ Ahi,
                  const __nv_bfloat16* __restrict__ Alo,
                  const __nv_bfloat16* __restrict__ Bhi,
                  const __nv_bfloat16* __restrict__ Blo,
                  const float* __restrict__ bias, int nbias,
                  float* __restrict__ C, int ldc)
{
    extern __shared__ __nv_bfloat16 smg[];
    const int tid  = threadIdx.x;
    const int lane = tid & 31;
    const int wid  = tid >> 5;
    const int m0 = blockIdx.y * 128;
    const int n0 = blockIdx.x * 128;
    const int wm = (wid & 3) << 5;     // warp m offset (0..96)
    const int wn = (wid >> 2) << 6;    // warp n offset (0 or 64)
    const uint32_t sbase = smem_u32(smg);

    const __nv_bfloat16* gsrc[4] = {
        Ahi + (size_t)m0 * K, Alo + (size_t)m0 * K,
        Bhi + (size_t)n0 * K, Blo + (size_t)n0 * K };

    const int lr = tid >> 2;           // 0..63
    const int lc = tid & 3;            // 16B chunk within BK row

    const int nch = K / BK;

    // ---- load chunk i into stage s ----
    auto load_chunk = [&](int i, int s) {
        const int k0 = i * BK;
        const uint32_t sb = sbase + (uint32_t)s * STAGE_H * 2;
        #pragma unroll
        for (int m = 0; m < 4; ++m) {
            const __nv_bfloat16* g = gsrc[m] + k0;
            const uint32_t sd = sb + m * TILE_H * 2;
            cp16(sd + (lr * RSTR + lc * 8) * 2,        g + (size_t)lr * K + lc * 8);
            cp16(sd + ((lr + 64) * RSTR + lc * 8) * 2, g + (size_t)(lr + 64) * K + lc * 8);
        }
        CP_COMMIT();
    };

    float acc[2][8][4];
    #pragma unroll
    for (int mt = 0; mt < 2; ++mt)
        #pragma unroll
        for (int nt = 0; nt < 8; ++nt)
            #pragma unroll
            for (int j = 0; j < 4; ++j) acc[mt][nt][j] = 0.f;

    load_chunk(0, 0);

    // ldmatrix lane addressing
    const int grp = lane >> 3, wi = lane & 7;
    const int a_row = ((grp & 1) << 3) + wi;   // + k hi via grp>>1
    const int a_kof = (grp >> 1) << 3;
    const int b_row = ((grp >> 1) << 3) + wi;
    const int b_kof = (grp & 1) << 3;

    for (int i = 0; i < nch; ++i) {
        if (i + 1 < nch) load_chunk(i + 1, (i + 1) & 1);
        if (i + 1 < nch) { CP_WAIT(1); } else { CP_WAIT(0); }
        __syncthreads();

        const uint32_t sb = sbase + (uint32_t)(i & 1) * STAGE_H * 2;
        const uint32_t sAh = sb;
        const uint32_t sAl = sb + TILE_H * 2;
        const uint32_t sBh = sb + 2 * TILE_H * 2;
        const uint32_t sBl = sb + 3 * TILE_H * 2;

        #pragma unroll
        for (int ks = 0; ks < 2; ++ks) {
            const int k0 = ks << 4;
            uint32_t Ahf[2][4], Alf[2][4], Bhf[4][4], Blf[4][4];
            #pragma unroll
            for (int mt = 0; mt < 2; ++mt) {
                uint32_t off = ((wm + mt * 16 + a_row) * RSTR + k0 + a_kof) * 2;
                ldsm_x4(Ahf[mt], sAh + off);
                ldsm_x4(Alf[mt], sAl + off);
            }
            #pragma unroll
            for (int bt = 0; bt < 4; ++bt) {
                uint32_t off = ((wn + bt * 16 + b_row) * RSTR + k0 + b_kof) * 2;
                ldsm_x4(Bhf[bt], sBh + off);
                ldsm_x4(Blf[bt], sBl + off);
            }
            #pragma unroll
            for (int mt = 0; mt < 2; ++mt)
                #pragma unroll
                for (int bt = 0; bt < 4; ++bt) {
                    mma16816(acc[mt][bt*2+0], Ahf[mt], Bhf[bt][0], Bhf[bt][1]);
                    mma16816(acc[mt][bt*2+1], Ahf[mt], Bhf[bt][2], Bhf[bt][3]);
                    mma16816(acc[mt][bt*2+0], Alf[mt], Bhf[bt][0], Bhf[bt][1]);
                    mma16816(acc[mt][bt*2+1], Alf[mt], Bhf[bt][2], Bhf[bt][3]);
                    mma16816(acc[mt][bt*2+0], Ahf[mt], Blf[bt][0], Blf[bt][1]);
                    mma16816(acc[mt][bt*2+1], Ahf[mt], Blf[bt][2], Blf[bt][3]);
                }
        }
        __syncthreads();
    }

    // epilogue: direct global stores + bias
    const int er = lane >> 2;
    const int ec = (lane & 3) * 2;
    #pragma unroll
    for (int mt = 0; mt < 2; ++mt) {
        #pragma unroll
        for (int nt = 0; nt < 8; ++nt) {
            int gm = m0 + wm + mt * 16 + er;
            int gn = n0 + wn + nt * 8 + ec;
            float b0 = (gn     < nbias) ? bias[gn]     : 0.f;
            float b1 = (gn + 1 < nbias) ? bias[gn + 1] : 0.f;
            C[(size_t)gm * ldc + gn]           = acc[mt][nt][0] + b0;
            C[(size_t)gm * ldc + gn + 1]       = acc[mt][nt][1] + b1;
            C[(size_t)(gm + 8) * ldc + gn]     = acc[mt][nt][2] + b0;
            C[(size_t)(gm + 8) * ldc + gn + 1] = acc[mt][nt][3] + b1;
        }
    }
}

// ----------------------------- split / transpose ----------------------------
__global__ __launch_bounds__(256)
void split_kernel(const float* __restrict__ X, int rows, int W, int stride,
                  __nv_bfloat16* __restrict__ hi, __nv_bfloat16* __restrict__ lo)
{
    int idx = blockIdx.x * 256 + threadIdx.x;
    if (idx >= rows * W) return;
    int r = idx / W, c = idx - r * W;
    float v = X[(size_t)r * stride + c];
    __nv_bfloat16 h = __float2bfloat16_rn(v);
    hi[idx] = h;
    lo[idx] = __float2bfloat16_rn(v - __bfloat162float(h));
}

// W[K,N] fp32 -> T[Npad,K] bf16 hi/lo (zero pad rows n>=N)
__global__ __launch_bounds__(256)
void transpose_split(const float* __restrict__ W, int K, int N, int /*Npad*/,
                     __nv_bfloat16* __restrict__ Thi, __nv_bfloat16* __restrict__ Tlo)
{
    __shared__ float t[32][33];
    int n0 = blockIdx.x * 32, k0 = blockIdx.y * 32;
    int x = threadIdx.x, y0 = threadIdx.y;      // 32 x 8
    #pragma unroll
    for (int i = 0; i < 4; ++i) {
        int k = k0 + y0 + i * 8;
        int n = n0 + x;
        t[y0 + i * 8][x] = (n < N) ? W[(size_t)k * N + n] : 0.f;
    }
    __syncthreads();
    #pragma unroll
    for (int i = 0; i < 4; ++i) {
        int n = n0 + y0 + i * 8;
        int k = k0 + x;
        float v = t[x][y0 + i * 8];
        __nv_bfloat16 h = __float2bfloat16_rn(v);
        Thi[(size_t)n * K + k] = h;
        Tlo[(size_t)n * K + k] = __float2bfloat16_rn(v - __bfloat162float(h));
    }
}

// ----------------------------- rmsnorm (in place) ---------------------------
__global__ __launch_bounds__(256)
void rmsnorm_kernel(float* __restrict__ x, const float* __restrict__ g,
                    int W, int stride)
{
    __shared__ float warp_s[8];
    int row = blockIdx.x;
    float* xr = x + (size_t)row * stride;

    float ss = 0.f;
    for (int j = threadIdx.x; j < W; j += 256) { float v = xr[j]; ss = fmaf(v, v, ss); }
    #pragma unroll
    for (int o = 16; o; o >>= 1) ss += __shfl_xor_sync(0xffffffffu, ss, o);
    if ((threadIdx.x & 31) == 0) warp_s[threadIdx.x >> 5] = ss;
    __syncthreads();
    if (threadIdx.x < 8) {
        float v = warp_s[threadIdx.x];
        #pragma unroll
        for (int o = 4; o; o >>= 1) v += __shfl_xor_sync(0xffu, v, o);
        if (threadIdx.x == 0) warp_s[0] = v;
    }
    __syncthreads();
    float inv = rsqrtf(warp_s[0] / (float)W + 1e-20f);
    for (int j = threadIdx.x; j < W; j += 256) xr[j] = xr[j] * inv * g[j];
}

// ----------------------------- RoPE helpers --------------------------------
__device__ __forceinline__ float2 rope_cs(int s, int idx)
{
    float t = (float)(2 * idx) / 64.0f;
    float inv_freq = 1.0f / powf(10000.0f, t);
    float ang = (float)s * inv_freq;
    return make_float2(cosf(ang), sinf(ang));
}

__global__ __launch_bounds__(256)
void rope_q_kernel(const float* __restrict__ qb, float* __restrict__ Q)
{
    int t = blockIdx.x * 256 + threadIdx.x;
    const int TOTAL = Bsz * NH * SEQ * DH_;
    if (t >= TOTAL) return;
    int j = t % DH_;
    int s = (t / DH_) % SEQ;
    int h = (t / (DH_ * SEQ)) % NH;
    int b = t / (DH_ * SEQ * NH);
    size_t src = ((size_t)(b * SEQ + s)) * (NH * DH_) + h * DH_;
    float val;
    if (j >= DR_) {
        val = qb[src + (j - DR_)];
    } else {
        float x   = qb[src + DN_ + j];
        float rot = (j < 32) ? -qb[src + DN_ + j + 32] : qb[src + DN_ + j - 32];
        int idx = (j < 32) ? j : j - 32;
        float2 cs = rope_cs(s, idx);
        val = x * cs.x + rot * cs.y;
    }
    Q[t] = val;
}

__global__ __launch_bounds__(256)
void build_kv_kernel(const float* __restrict__ kva, const float* __restrict__ kvb,
                     float* __restrict__ K, float* __restrict__ V)
{
    int t = blockIdx.x * 256 + threadIdx.x;
    const int PER = DH_ + DV_;
    const int TOTAL = Bsz * NKV * SEQ * PER;
    if (t >= TOTAL) return;
    int j = t % PER;
    int s = (t / PER) % SEQ;
    int g = (t / (PER * SEQ)) % NKV;
    int b = t / (PER * SEQ * NKV);
    size_t rowa = ((size_t)(b * SEQ + s)) * KVAPAD;
    size_t rowb = ((size_t)(b * SEQ + s)) * (NKV * (DN_ + DV_)) + g * (DN_ + DV_);
    if (j < DH_) {
        float val;
        if (j < DR_) {
            float x   = kva[rowa + RKV_ + j];
            float rot = (j < 32) ? -kva[rowa + RKV_ + j + 32] : kva[rowa + RKV_ + j - 32];
            int idx = (j < 32) ? j : j - 32;
            float2 cs = rope_cs(s, idx);
            val = x * cs.x + rot * cs.y;
        } else {
            val = kvb[rowb + (j - DR_)];
        }
        K[(((size_t)(b * NKV + g)) * SEQ + s) * DH_ + j] = val;
    } else {
        V[(((size_t)(b * NKV + g)) * SEQ + s) * DV_ + (j - DH_)] =
            kvb[rowb + DN_ + (j - DH_)];
    }
}

// ----------------------------- flash attention (fp32) ----------------------
#define AQ 64
#define AK 32
#define KS_STRIDE 36
#define PS_STRIDE 68

#define SM_QS    0
#define SM_KS    (SM_QS + AQ*DH_)
#define SM_VS    (SM_KS + DH_*KS_STRIDE)
#define SM_SS    (SM_VS + AK*DV_)
#define SM_PS    (SM_SS + AQ*33)
#define SM_M     (SM_PS + AK*PS_STRIDE)
#define SM_L     (SM_M + AQ)
#define SM_AL    (SM_L + AQ)
#define SM_TOTAL (SM_AL + AQ)
#define ATTN_SMEM_BYTES (SM_TOTAL * 4)

__global__ __launch_bounds__(256)
void attn_kernel(const float* __restrict__ Q, const float* __restrict__ K,
                 const float* __restrict__ V, float* __restrict__ Out)
{
    extern __shared__ float sm[];
    float* Qs = sm + SM_QS;
    float* Ks = sm + SM_KS;
    float* Vs = sm + SM_VS;
    float* Ss = sm + SM_SS;
    float* Ps = sm + SM_PS;
    float* m_s  = sm + SM_M;
    float* l_s  = sm + SM_L;
    float* al_s = sm + SM_AL;

    const int tid = threadIdx.x;
    const int q0 = blockIdx.x * AQ;
    const int h  = blockIdx.y;
    const int b  = blockIdx.z;
    const int g  = h >> 2;
    const float scale = 1.0f / sqrtf((float)DH_);

    const float* Qg = Q + (((size_t)(b * NH + h)) * SEQ + q0) * DH_;
    const float* Kg = K + ((size_t)(b * NKV + g)) * SEQ * DH_;
    const float* Vg = V + ((size_t)(b * NKV + g)) * SEQ * DV_;

    for (int idx = tid; idx < AQ * DH_ / 4; idx += 256)
        reinterpret_cast<float4*>(Qs)[idx] =
            reinterpret_cast<const float4*>(Qg)[idx];
    if (tid < AQ) { m_s[tid] = -INFINITY; l_s[tid] = 0.f; }

    const int ty = tid >> 4;
    const int tx = tid & 15;

    float o[4][8];
    #pragma unroll
    for (int i = 0; i < 4; i++)
        #pragma unroll
        for (int j = 0; j < 8; j++) o[i][j] = 0.f;

    const int kend = q0 + AQ;
    for (int ks = 0; ks < kend; ks += AK) {
        __syncthreads();
        for (int idx = tid; idx < AK * (DH_ / 4); idx += 256) {
            int c  = idx / (DH_ / 4);
            int d4 = idx % (DH_ / 4);
            float4 kv = reinterpret_cast<const float4*>(
                Kg + (size_t)(ks + c) * DH_)[d4];
            Ks[(d4*4+0)*KS_STRIDE + c] = kv.x;
            Ks[(d4*4+1)*KS_STRIDE + c] = kv.y;
            Ks[(d4*4+2)*KS_STRIDE + c] = kv.z;
            Ks[(d4*4+3)*KS_STRIDE + c] = kv.w;
        }
        for (int idx = tid; idx < AK * DV_ / 4; idx += 256)
            reinterpret_cast<float4*>(Vs)[idx] =
                reinterpret_cast<const float4*>(Vg + (size_t)ks * DV_)[idx];
        __syncthreads();

        float sc[4][2];
        #pragma unroll
        for (int i = 0; i < 4; i++) { sc[i][0] = 0.f; sc[i][1] = 0.f; }
        #pragma unroll 4
        for (int d = 0; d < DH_; d++) {
            float2 kvv = *reinterpret_cast<float2*>(&Ks[d*KS_STRIDE + tx*2]);
            #pragma unroll
            for (int i = 0; i < 4; i++) {
                float qv = Qs[(ty*4+i)*DH_ + d];
                sc[i][0] = fmaf(qv, kvv.x, sc[i][0]);
                sc[i][1] = fmaf(qv, kvv.y, sc[i][1]);
            }
        }
        #pragma unroll
        for (int i = 0; i < 4; i++) {
            Ss[(ty*4+i)*33 + tx*2 + 0] = sc[i][0];
            Ss[(ty*4+i)*33 + tx*2 + 1] = sc[i][1];
        }
        __syncthreads();

        {
            int r  = tid >> 2;
            int qd = tid & 3;
            float m_old = m_s[r];
            float mx = m_old;
            #pragma unroll 8
            for (int c = 0; c < AK; c++) {
                float sv = (ks + c <= q0 + r) ? Ss[r*33 + c] * scale : -INFINITY;
                mx = fmaxf(mx, sv);
            }
            float alpha = expf(m_old - mx);
            float lsum = 0.f;
            #pragma unroll
            for (int c = qd * 8; c < qd * 8 + 8; c++) {
                float sv = (ks + c <= q0 + r) ? Ss[r*33 + c] * scale : -INFINITY;
                float p = expf(sv - mx);
                Ps[c*PS_STRIDE + r] = p;
                lsum += p;
            }
            lsum += __shfl_xor_sync(0xffffffffu, lsum, 1);
            lsum += __shfl_xor_sync(0xffffffffu, lsum, 2);
            if (qd == 0) {
                m_s[r]  = mx;
                l_s[r]  = l_s[r] * alpha + lsum;
                al_s[r] = alpha;
            }
        }
        __syncthreads();

        {
            #pragma unroll
            for (int i = 0; i < 4; i++) {
                float al = al_s[ty*4 + i];
                #pragma unroll
                for (int j = 0; j < 8; j++) o[i][j] *= al;
            }
            #pragma unroll 4
            for (int c = 0; c < AK; c++) {
                float4 p4 = *reinterpret_cast<float4*>(&Ps[c*PS_STRIDE + ty*4]);
                float pv[4] = {p4.x, p4.y, p4.z, p4.w};
                float4 v0 = *reinterpret_cast<float4*>(&Vs[c*DV_ + tx*8]);
                float4 v1 = *reinterpret_cast<float4*>(&Vs[c*DV_ + tx*8 + 4]);
                float vv[8] = {v0.x,v0.y,v0.z,v0.w,v1.x,v1.y,v1.z,v1.w};
                #pragma unroll
                for (int i = 0; i < 4; i++)
                    #pragma unroll
                    for (int j = 0; j < 8; j++)
                        o[i][j] = fmaf(pv[i], vv[j], o[i][j]);
            }
        }
    }

    #pragma unroll
    for (int i = 0; i < 4; i++) {
        int r = ty*4 + i;
        float invl = 1.0f / l_s[r];
        size_t orow = ((size_t)(b * SEQ + q0 + r)) * (NH * DV_) + h * DV_ + tx*8;
        float4 w0, w1;
        w0.x = o[i][0]*invl; w0.y = o[i][1]*invl; w0.z = o[i][2]*invl; w0.w = o[i][3]*invl;
        w1.x = o[i][4]*invl; w1.y = o[i][5]*invl; w1.z = o[i][6]*invl; w1.w = o[i][7]*invl;
        *reinterpret_cast<float4*>(&Out[orow])     = w0;
        *reinterpret_cast<float4*>(&Out[orow + 4]) = w1;
    }
}

// ----------------------------- host ----------------------------------------
extern "C" void kernel_launch(void* const* d_in, const int* in_sizes, int n_in,
                              void* d_out, int out_size)
{
    const float* X     = (const float*)d_in[0];
    const float* w_qa  = (const float*)d_in[2];
    const float* b_qa  = (const float*)d_in[3];
    const float* gq    = (const float*)d_in[4];
    const float* w_qb  = (const float*)d_in[5];
    const float* b_qb  = (const float*)d_in[6];
    const float* w_kva = (const float*)d_in[7];
    const float* b_kva = (const float*)d_in[8];
    const float* gkv   = (const float*)d_in[9];
    const float* w_kvb = (const float*)d_in[10];
    const float* b_kvb = (const float*)d_in[11];
    const float* w_o   = (const float*)d_in[12];
    const float* b_o   = (const float*)d_in[13];
    float* out = (float*)d_out;

    float *qa, *qb, *kva, *kvb, *Q, *K, *V, *attn;
    cudaGetSymbolAddress((void**)&qa,  g_qa);
    cudaGetSymbolAddress((void**)&qb,  g_qb);
    cudaGetSymbolAddress((void**)&kva, g_kva);
    cudaGetSymbolAddress((void**)&kvb, g_kvb);
    cudaGetSymbolAddress((void**)&Q,   g_Q);
    cudaGetSymbolAddress((void**)&K,   g_K);
    cudaGetSymbolAddress((void**)&V,   g_V);
    cudaGetSymbolAddress((void**)&attn,g_attn);

    __nv_bfloat16 *Xhi, *Xlo, *QAhi, *QAlo, *KVAhi, *KVAlo, *AThi, *ATlo;
    __nv_bfloat16 *Wqah, *Wqal, *Wqbh, *Wqbl, *Wkvah, *Wkval, *Wkvbh, *Wkvbl, *Woh, *Wol;
    cudaGetSymbolAddress((void**)&Xhi,  g_Xhi);
    cudaGetSymbolAddress((void**)&Xlo,  g_Xlo);
    cudaGetSymbolAddress((void**)&QAhi, g_QAhi);
    cudaGetSymbolAddress((void**)&QAlo, g_QAlo);
    cudaGetSymbolAddress((void**)&KVAhi,g_KVAhi);
    cudaGetSymbolAddress((void**)&KVAlo,g_KVAlo);
    cudaGetSymbolAddress((void**)&AThi, g_AThi);
    cudaGetSymbolAddress((void**)&ATlo, g_ATlo);
    cudaGetSymbolAddress((void**)&Wqah, g_Wqa_hi);
    cudaGetSymbolAddress((void**)&Wqal, g_Wqa_lo);
    cudaGetSymbolAddress((void**)&Wqbh, g_Wqb_hi);
    cudaGetSymbolAddress((void**)&Wqbl, g_Wqb_lo);
    cudaGetSymbolAddress((void**)&Wkvah,g_Wkva_hi);
    cudaGetSymbolAddress((void**)&Wkval,g_Wkva_lo);
    cudaGetSymbolAddress((void**)&Wkvbh,g_Wkvb_hi);
    cudaGetSymbolAddress((void**)&Wkvbl,g_Wkvb_lo);
    cudaGetSymbolAddress((void**)&Woh,  g_Wo_hi);
    cudaGetSymbolAddress((void**)&Wol,  g_Wo_lo);

    cudaFuncSetAttribute(tc_gemm_bias,
        cudaFuncAttributeMaxDynamicSharedMemorySize, TC_SMEM_BYTES);
    cudaFuncSetAttribute(attn_kernel,
        cudaFuncAttributeMaxDynamicSharedMemorySize, ATTN_SMEM_BYTES);

    dim3 tpb(32, 8);

    // weight prep (transpose + bf16 split)
    transpose_split<<<dim3(RQ_/32, DMODEL/32), tpb>>>(w_qa, DMODEL, RQ_, RQ_, Wqah, Wqal);
    transpose_split<<<dim3((NH*DH_)/32, RQ_/32), tpb>>>(w_qb, RQ_, NH*DH_, NH*DH_, Wqbh, Wqbl);
    transpose_split<<<dim3(KVAPAD/32, DMODEL/32), tpb>>>(w_kva, DMODEL, RKV_+DR_, KVAPAD, Wkvah, Wkval);
    transpose_split<<<dim3((NKV*(DN_+DV_))/32, RKV_/32), tpb>>>(w_kvb, RKV_, NKV*(DN_+DV_), NKV*(DN_+DV_), Wkvbh, Wkvbl);
    transpose_split<<<dim3(DMODEL/32, (NH*DV_)/32), tpb>>>(w_o, NH*DV_, DMODEL, DMODEL, Woh, Wol);

    // X split
    split_kernel<<<(ROWS*DMODEL + 255)/256, 256>>>(X, ROWS, DMODEL, DMODEL, Xhi, Xlo);

    // q path
    tc_gemm_bias<<<dim3(RQ_/128, ROWS/128), 256, TC_SMEM_BYTES>>>(
        ROWS, RQ_, DMODEL, Xhi, Xlo, Wqah, Wqal, b_qa, RQ_, qa, RQ_);
    rmsnorm_kernel<<<ROWS, 256>>>(qa, gq, RQ_, RQ_);
    split_kernel<<<(ROWS*RQ_ + 255)/256, 256>>>(qa, ROWS, RQ_, RQ_, QAhi, QAlo);
    tc_gemm_bias<<<dim3((NH*DH_)/128, ROWS/128), 256, TC_SMEM_BYTES>>>(
        ROWS, NH*DH_, RQ_, QAhi, QAlo, Wqbh, Wqbl, b_qb, NH*DH_, qb, NH*DH_);

    // kv path (N padded 576->640)
    tc_gemm_bias<<<dim3(KVAPAD/128, ROWS/128), 256, TC_SMEM_BYTES>>>(
        ROWS, KVAPAD, DMODEL, Xhi, Xlo, Wkvah, Wkval, b_kva, RKV_+DR_, kva, KVAPAD);
    rmsnorm_kernel<<<ROWS, 256>>>(kva, gkv, RKV_, KVAPAD);
    split_kernel<<<(ROWS*RKV_ + 255)/256, 256>>>(kva, ROWS, RKV_, KVAPAD, KVAhi, KVAlo);
    tc_gemm_bias<<<dim3((NKV*(DN_+DV_))/128, ROWS/128), 256, TC_SMEM_BYTES>>>(
        ROWS, NKV*(DN_+DV_), RKV_, KVAhi, KVAlo, Wkvbh, Wkvbl, b_kvb, NKV*(DN_+DV_), kvb, NKV*(DN_+DV_));

    // rope + layout
    {
        int n1 = Bsz*NH*SEQ*DH_;
        rope_q_kernel<<<(n1 + 255)/256, 256>>>(qb, Q);
        int n2 = Bsz*NKV*SEQ*(DH_+DV_);
        build_kv_kernel<<<(n2 + 255)/256, 256>>>(kva, kvb, K, V);
    }

    // attention (fp32)
    attn_kernel<<<dim3(SEQ/AQ, NH, Bsz), 256, ATTN_SMEM_BYTES>>>(Q, K, V, attn);

    // out projection
    split_kernel<<<(ROWS*(NH*DV_) + 255)/256, 256>>>(attn, ROWS, NH*DV_, NH*DV_, AThi, ATlo);
    tc_gemm_bias<<<dim3(DMODEL/128, ROWS/128), 256, TC_SMEM_BYTES>>>(
        ROWS, DMODEL, NH*DV_, AThi, ATlo, Woh, Wol, b_o, DMODEL, out, DMODEL);
}

// round 4
// speedup vs baseline: 2.9776x; 2.1289x over previous
#include <cuda_runtime.h>
#include <cuda_bf16.h>
#include <math.h>
#include <stdint.h>

// ---------------------------------------------------------------------------
// Multi-Latent Attention — mma.sync bf16x3 GEMMs + bf16x3 mma flash attention
// B=2 S=2048 D=2048 H=16 HKV=4 RQ=1024 RKV=512 DH=192 DR=64 DN=128 DV=128
// ---------------------------------------------------------------------------

#define Bsz   2
#define SEQ   2048
#define DMODEL 2048
#define NH    16
#define NKV   4
#define RQ_   1024
#define RKV_  512
#define DH_   192
#define DR_   64
#define DN_   128
#define DV_   128
#define ROWS  (Bsz*SEQ)          // 4096
#define KVAPAD 640               // kv_a N padded 576 -> 640

// ----------------------------- scratch (fp32) ------------------------------
__device__ float g_qa [ROWS * RQ_];
__device__ float g_qb [ROWS * (NH*DH_)];
__device__ float g_kva[ROWS * KVAPAD];
__device__ float g_kvb[ROWS * (NKV*(DN_+DV_))];

// ----------------------------- scratch (bf16) -------------------------------
__device__ __nv_bfloat16 g_Xhi [ROWS*DMODEL];
__device__ __nv_bfloat16 g_Xlo [ROWS*DMODEL];
__device__ __nv_bfloat16 g_QAhi[ROWS*RQ_];
__device__ __nv_bfloat16 g_QAlo[ROWS*RQ_];
__device__ __nv_bfloat16 g_KVAhi[ROWS*RKV_];
__device__ __nv_bfloat16 g_KVAlo[ROWS*RKV_];
__device__ __nv_bfloat16 g_AThi[ROWS*(NH*DV_)];
__device__ __nv_bfloat16 g_ATlo[ROWS*(NH*DV_)];
// attention operands, split
__device__ __nv_bfloat16 g_Qhi [Bsz*NH *SEQ*DH_];
__device__ __nv_bfloat16 g_Qlo [Bsz*NH *SEQ*DH_];
__device__ __nv_bfloat16 g_Khi [Bsz*NKV*SEQ*DH_];
__device__ __nv_bfloat16 g_Klo [Bsz*NKV*SEQ*DH_];
__device__ __nv_bfloat16 g_Vhi [Bsz*NKV*SEQ*DV_];
__device__ __nv_bfloat16 g_Vlo [Bsz*NKV*SEQ*DV_];
// transposed weights [N][K] bf16 hi/lo
__device__ __nv_bfloat16 g_Wqa_hi [RQ_ * DMODEL];
__device__ __nv_bfloat16 g_Wqa_lo [RQ_ * DMODEL];
__device__ __nv_bfloat16 g_Wqb_hi [(NH*DH_) * RQ_];
__device__ __nv_bfloat16 g_Wqb_lo [(NH*DH_) * RQ_];
__device__ __nv_bfloat16 g_Wkva_hi[KVAPAD * DMODEL];
__device__ __nv_bfloat16 g_Wkva_lo[KVAPAD * DMODEL];
__device__ __nv_bfloat16 g_Wkvb_hi[(NKV*(DN_+DV_)) * RKV_];
__device__ __nv_bfloat16 g_Wkvb_lo[(NKV*(DN_+DV_)) * RKV_];
__device__ __nv_bfloat16 g_Wo_hi  [DMODEL * (NH*DV_)];
__device__ __nv_bfloat16 g_Wo_lo  [DMODEL * (NH*DV_)];

// ----------------------------- PTX helpers ---------------------------------
__device__ __forceinline__ uint32_t smem_u32(const void* p) {
    uint32_t a;
    asm("{ .reg .u64 t; cvta.to.shared.u64 t, %1; cvt.u32.u64 %0, t; }"
        : "=r"(a) : "l"(p));
    return a;
}
__device__ __forceinline__ void cp16(uint32_t dst, const void* src) {
    asm volatile("cp.async.cg.shared.global [%0], [%1], 16;"
                 :: "r"(dst), "l"(src) : "memory");
}
#define CP_COMMIT() asm volatile("cp.async.commit_group;" ::: "memory")
#define CP_WAIT(n)  asm volatile("cp.async.wait_group %0;" :: "n"(n) : "memory")

__device__ __forceinline__ void ldsm_x4(uint32_t* r, uint32_t addr) {
    asm volatile("ldmatrix.sync.aligned.m8n8.x4.shared.b16 {%0,%1,%2,%3}, [%4];"
                 : "=r"(r[0]), "=r"(r[1]), "=r"(r[2]), "=r"(r[3]) : "r"(addr));
}
__device__ __forceinline__ void ldsm_x4_t(uint32_t* r, uint32_t addr) {
    asm volatile("ldmatrix.sync.aligned.m8n8.x4.trans.shared.b16 {%0,%1,%2,%3}, [%4];"
                 : "=r"(r[0]), "=r"(r[1]), "=r"(r[2]), "=r"(r[3]) : "r"(addr));
}
__device__ __forceinline__ void mma16816(float* c, const uint32_t* a,
                                         uint32_t b0, uint32_t b1) {
    asm volatile(
        "mma.sync.aligned.m16n8k16.row.col.f32.bf16.bf16.f32 "
        "{%0,%1,%2,%3}, {%4,%5,%6,%7}, {%8,%9}, {%0,%1,%2,%3};"
        : "+f"(c[0]), "+f"(c[1]), "+f"(c[2]), "+f"(c[3])
        : "r"(a[0]), "r"(a[1]), "r"(a[2]), "r"(a[3]), "r"(b0), "r"(b1));
}

// ----------------------------- tc GEMM (mma.sync bf16x3) --------------------
#define BK    32
#define RSTR  40
#define TILE_H (128*RSTR)
#define STAGE_H (4*TILE_H)
#define TC_SMEM_BYTES (2*STAGE_H*2)

__global__ __launch_bounds__(256)
void tc_gemm_bias(int M, int N, int K,
                  const __nv_bfloat16* __restrict__ Ahi,
                  const __nv_bfloat16* __restrict__ Alo,
                  const __nv_bfloat16* __restrict__ Bhi,
                  const __nv_bfloat16* __restrict__ Blo,
                  const float* __restrict__ bias, int nbias,
                  float* __restrict__ C, int ldc)
{
    extern __shared__ __nv_bfloat16 smg[];
    const int tid  = threadIdx.x;
    const int lane = tid & 31;
    const int wid  = tid >> 5;
    const int m0 = blockIdx.y * 128;
    const int n0 = blockIdx.x * 128;
    const int wm = (wid & 3) << 5;
    const int wn = (wid >> 2) << 6;
    const uint32_t sbase = smem_u32(smg);

    const __nv_bfloat16* gsrc[4] = {
        Ahi + (size_t)m0 * K, Alo + (size_t)m0 * K,
        Bhi + (size_t)n0 * K, Blo + (size_t)n0 * K };

    const int lr = tid >> 2;
    const int lc = tid & 3;
    const int nch = K / BK;

    auto load_chunk = [&](int i, int s) {
        const int k0 = i * BK;
        const uint32_t sb = sbase + (uint32_t)s * STAGE_H * 2;
        #pragma unroll
        for (int m = 0; m < 4; ++m) {
            const __nv_bfloat16* g = gsrc[m] + k0;
            const uint32_t sd = sb + m * TILE_H * 2;
            cp16(sd + (lr * RSTR + lc * 8) * 2,        g + (size_t)lr * K + lc * 8);
            cp16(sd + ((lr + 64) * RSTR + lc * 8) * 2, g + (size_t)(lr + 64) * K + lc * 8);
        }
        CP_COMMIT();
    };

    float acc[2][8][4];
    #pragma unroll
    for (int mt = 0; mt < 2; ++mt)
        #pragma unroll
        for (int nt = 0; nt < 8; ++nt)
            #pragma unroll
            for (int j = 0; j < 4; ++j) acc[mt][nt][j] = 0.f;

    load_chunk(0, 0);

    const int grp = lane >> 3, wi = lane & 7;
    const int a_row = ((grp & 1) << 3) + wi;
    const int a_kof = (grp >> 1) << 3;
    const int b_row = ((grp >> 1) << 3) + wi;
    const int b_kof = (grp & 1) << 3;

    for (int i = 0; i < nch; ++i) {
        if (i + 1 < nch) load_chunk(i + 1, (i + 1) & 1);
        if (i + 1 < nch) { CP_WAIT(1); } else { CP_WAIT(0); }
        __syncthreads();

        const uint32_t sb = sbase + (uint32_t)(i & 1) * STAGE_H * 2;
        const uint32_t sAh = sb;
        const uint32_t sAl = sb + TILE_H * 2;
        const uint32_t sBh = sb + 2 * TILE_H * 2;
        const uint32_t sBl = sb + 3 * TILE_H * 2;

        #pragma unroll
        for (int ks = 0; ks < 2; ++ks) {
            const int k0 = ks << 4;
            uint32_t Ahf[2][4], Alf[2][4], Bhf[4][4], Blf[4][4];
            #pragma unroll
            for (int mt = 0; mt < 2; ++mt) {
                uint32_t off = ((wm + mt * 16 + a_row) * RSTR + k0 + a_kof) * 2;
                ldsm_x4(Ahf[mt], sAh + off);
                ldsm_x4(Alf[mt], sAl + off);
            }
            #pragma unroll
            for (int bt = 0; bt < 4; ++bt) {
                uint32_t off = ((wn + bt * 16 + b_row) * RSTR + k0 + b_kof) * 2;
                ldsm_x4(Bhf[bt], sBh + off);
                ldsm_x4(Blf[bt], sBl + off);
            }
            #pragma unroll
            for (int mt = 0; mt < 2; ++mt)
                #pragma unroll
                for (int bt = 0; bt < 4; ++bt) {
                    mma16816(acc[mt][bt*2+0], Ahf[mt], Bhf[bt][0], Bhf[bt][1]);
                    mma16816(acc[mt][bt*2+1], Ahf[mt], Bhf[bt][2], Bhf[bt][3]);
                    mma16816(acc[mt][bt*2+0], Alf[mt], Bhf[bt][0], Bhf[bt][1]);
                    mma16816(acc[mt][bt*2+1], Alf[mt], Bhf[bt][2], Bhf[bt][3]);
                    mma16816(acc[mt][bt*2+0], Ahf[mt], Blf[bt][0], Blf[bt][1]);
                    mma16816(acc[mt][bt*2+1], Ahf[mt], Blf[bt][2], Blf[bt][3]);
                }
        }
        __syncthreads();
    }

    const int er = lane >> 2;
    const int ec = (lane & 3) * 2;
    #pragma unroll
    for (int mt = 0; mt < 2; ++mt) {
        #pragma unroll
        for (int nt = 0; nt < 8; ++nt) {
            int gm = m0 + wm + mt * 16 + er;
            int gn = n0 + wn + nt * 8 + ec;
            float b0 = (gn     < nbias) ? bias[gn]     : 0.f;
            float b1 = (gn + 1 < nbias) ? bias[gn + 1] : 0.f;
            C[(size_t)gm * ldc + gn]           = acc[mt][nt][0] + b0;
            C[(size_t)gm * ldc + gn + 1]       = acc[mt][nt][1] + b1;
            C[(size_t)(gm + 8) * ldc + gn]     = acc[mt][nt][2] + b0;
            C[(size_t)(gm + 8) * ldc + gn + 1] = acc[mt][nt][3] + b1;
        }
    }
}

// ----------------------------- split / transpose ----------------------------
__global__ __launch_bounds__(256)
void split_kernel(const float* __restrict__ X, int rows, int W, int stride,
                  __nv_bfloat16* __restrict__ hi, __nv_bfloat16* __restrict__ lo)
{
    int idx = blockIdx.x * 256 + threadIdx.x;
    if (idx >= rows * W) return;
    int r = idx / W, c = idx - r * W;
    float v = X[(size_t)r * stride + c];
    __nv_bfloat16 h = __float2bfloat16_rn(v);
    hi[idx] = h;
    lo[idx] = __float2bfloat16_rn(v - __bfloat162float(h));
}

__global__ __launch_bounds__(256)
void transpose_split(const float* __restrict__ W, int K, int N, int /*Npad*/,
                     __nv_bfloat16* __restrict__ Thi, __nv_bfloat16* __restrict__ Tlo)
{
    __shared__ float t[32][33];
    int n0 = blockIdx.x * 32, k0 = blockIdx.y * 32;
    int x = threadIdx.x, y0 = threadIdx.y;
    #pragma unroll
    for (int i = 0; i < 4; ++i) {
        int k = k0 + y0 + i * 8;
        int n = n0 + x;
        t[y0 + i * 8][x] = (n < N) ? W[(size_t)k * N + n] : 0.f;
    }
    __syncthreads();
    #pragma unroll
    for (int i = 0; i < 4; ++i) {
        int n = n0 + y0 + i * 8;
        int k = k0 + x;
        float v = t[x][y0 + i * 8];
        __nv_bfloat16 h = __float2bfloat16_rn(v);
        Thi[(size_t)n * K + k] = h;
        Tlo[(size_t)n * K + k] = __float2bfloat16_rn(v - __bfloat162float(h));
    }
}

// ----------------------------- rmsnorm (in place) ---------------------------
__global__ __launch_bounds__(256)
void rmsnorm_kernel(float* __restrict__ x, const float* __restrict__ g,
                    int W, int stride)
{
    __shared__ float warp_s[8];
    int row = blockIdx.x;
    float* xr = x + (size_t)row * stride;

    float ss = 0.f;
    for (int j = threadIdx.x; j < W; j += 256) { float v = xr[j]; ss = fmaf(v, v, ss); }
    #pragma unroll
    for (int o = 16; o; o >>= 1) ss += __shfl_xor_sync(0xffffffffu, ss, o);
    if ((threadIdx.x & 31) == 0) warp_s[threadIdx.x >> 5] = ss;
    __syncthreads();
    if (threadIdx.x < 8) {
        float v = warp_s[threadIdx.x];
        #pragma unroll
        for (int o = 4; o; o >>= 1) v += __shfl_xor_sync(0xffu, v, o);
        if (threadIdx.x == 0) warp_s[0] = v;
    }
    __syncthreads();
    float inv = rsqrtf(warp_s[0] / (float)W + 1e-20f);
    for (int j = threadIdx.x; j < W; j += 256) xr[j] = xr[j] * inv * g[j];
}

// ----------------------------- RoPE + split --------------------------------
__device__ __forceinline__ float2 rope_cs(int s, int idx)
{
    float t = (float)(2 * idx) / 64.0f;
    float inv_freq = 1.0f / powf(10000.0f, t);
    float ang = (float)s * inv_freq;
    return make_float2(cosf(ang), sinf(ang));
}

// q_b [4096,H*192] -> Qhi/Qlo [B,H,S,192] ([rope|nrope])
__global__ __launch_bounds__(256)
void rope_q_split(const float* __restrict__ qb,
                  __nv_bfloat16* __restrict__ Qhi, __nv_bfloat16* __restrict__ Qlo)
{
    int t = blockIdx.x * 256 + threadIdx.x;
    const int TOTAL = Bsz * NH * SEQ * DH_;
    if (t >= TOTAL) return;
    int j = t % DH_;
    int s = (t / DH_) % SEQ;
    int h = (t / (DH_ * SEQ)) % NH;
    int b = t / (DH_ * SEQ * NH);
    size_t src = ((size_t)(b * SEQ + s)) * (NH * DH_) + h * DH_;
    float val;
    if (j >= DR_) {
        val = qb[src + (j - DR_)];
    } else {
        float x   = qb[src + DN_ + j];
        float rot = (j < 32) ? -qb[src + DN_ + j + 32] : qb[src + DN_ + j - 32];
        int idx = (j < 32) ? j : j - 32;
        float2 cs = rope_cs(s, idx);
        val = x * cs.x + rot * cs.y;
    }
    __nv_bfloat16 hh = __float2bfloat16_rn(val);
    Qhi[t] = hh;
    Qlo[t] = __float2bfloat16_rn(val - __bfloat162float(hh));
}

// kv_a/kv_b -> Khi/Klo [B,HKV,S,192], Vhi/Vlo [B,HKV,S,128]
__global__ __launch_bounds__(256)
void build_kv_split(const float* __restrict__ kva, const float* __restrict__ kvb,
                    __nv_bfloat16* __restrict__ Khi, __nv_bfloat16* __restrict__ Klo,
                    __nv_bfloat16* __restrict__ Vhi, __nv_bfloat16* __restrict__ Vlo)
{
    int t = blockIdx.x * 256 + threadIdx.x;
    const int PER = DH_ + DV_;
    const int TOTAL = Bsz * NKV * SEQ * PER;
    if (t >= TOTAL) return;
    int j = t % PER;
    int s = (t / PER) % SEQ;
    int g = (t / (PER * SEQ)) % NKV;
    int b = t / (PER * SEQ * NKV);
    size_t rowa = ((size_t)(b * SEQ + s)) * KVAPAD;
    size_t rowb = ((size_t)(b * SEQ + s)) * (NKV * (DN_ + DV_)) + g * (DN_ + DV_);
    if (j < DH_) {
        float val;
        if (j < DR_) {
            float x   = kva[rowa + RKV_ + j];
            float rot = (j < 32) ? -kva[rowa + RKV_ + j + 32] : kva[rowa + RKV_ + j - 32];
            int idx = (j < 32) ? j : j - 32;
            float2 cs = rope_cs(s, idx);
            val = x * cs.x + rot * cs.y;
        } else {
            val = kvb[rowb + (j - DR_)];
        }
        size_t o = (((size_t)(b * NKV + g)) * SEQ + s) * DH_ + j;
        __nv_bfloat16 hh = __float2bfloat16_rn(val);
        Khi[o] = hh;
        Klo[o] = __float2bfloat16_rn(val - __bfloat162float(hh));
    } else {
        float val = kvb[rowb + DN_ + (j - DH_)];
        size_t o = (((size_t)(b * NKV + g)) * SEQ + s) * DV_ + (j - DH_);
        __nv_bfloat16 hh = __float2bfloat16_rn(val);
        Vhi[o] = hh;
        Vlo[o] = __float2bfloat16_rn(val - __bfloat162float(hh));
    }
}

// ----------------------------- mma flash attention --------------------------
// 128 q rows / CTA, 8 warps x m16. K tiles of 64. bf16x3 everywhere.
#define ABQ 128
#define ABK 64
#define QSTR 200
#define KSTR 200
#define VSTR 136
#define B_QH 0
#define B_QL 51200
#define B_KH 102400
#define B_KL 128000
#define B_VH 153600
#define B_VL 171008
#define ATTN_SMEM 188416

__global__ __launch_bounds__(256)
void attn_mma(const __nv_bfloat16* __restrict__ Qhg, const __nv_bfloat16* __restrict__ Qlg,
              const __nv_bfloat16* __restrict__ Khg, const __nv_bfloat16* __restrict__ Klg,
              const __nv_bfloat16* __restrict__ Vhg, const __nv_bfloat16* __restrict__ Vlg,
              __nv_bfloat16* __restrict__ Ohi, __nv_bfloat16* __restrict__ Olo)
{
    extern __shared__ __nv_bfloat16 sma[];
    const uint32_t sbase = smem_u32(sma);
    const int tid = threadIdx.x;
    const int lane = tid & 31;
    const int w = tid >> 5;
    const int q0 = blockIdx.x * ABQ;
    const int h  = blockIdx.y;
    const int b  = blockIdx.z;
    const int g  = h >> 2;
    const float scale = rsqrtf((float)DH_);

    const __nv_bfloat16* Qh = Qhg + (((size_t)(b * NH + h)) * SEQ + q0) * DH_;
    const __nv_bfloat16* Ql = Qlg + (((size_t)(b * NH + h)) * SEQ + q0) * DH_;
    const __nv_bfloat16* Kh = Khg + ((size_t)(b * NKV + g)) * SEQ * DH_;
    const __nv_bfloat16* Kl = Klg + ((size_t)(b * NKV + g)) * SEQ * DH_;
    const __nv_bfloat16* Vh = Vhg + ((size_t)(b * NKV + g)) * SEQ * DV_;
    const __nv_bfloat16* Vl = Vlg + ((size_t)(b * NKV + g)) * SEQ * DV_;

    // load Q tile (hi+lo), 128 rows x 24 16B-chunks each
    for (int idx = tid; idx < ABQ * 24; idx += 256) {
        int r = idx / 24, c = (idx % 24) * 8;
        cp16(sbase + B_QH + (r * QSTR + c) * 2, Qh + (size_t)r * DH_ + c);
        cp16(sbase + B_QL + (r * QSTR + c) * 2, Ql + (size_t)r * DH_ + c);
    }
    CP_COMMIT();

    const int grp = lane >> 3, wi = lane & 7;
    const int a_row = ((grp & 1) << 3) + wi;
    const int a_kof = (grp >> 1) << 3;
    const int b_row = ((grp >> 1) << 3) + wi;
    const int b_kof = (grp & 1) << 3;
    const int q0w = q0 + w * 16;
    const int r_in = lane >> 2;          // row within m16 (also +8)
    const int c2   = (lane & 3) * 2;     // col pair base within n8

    float o[16][4];
    #pragma unroll
    for (int i = 0; i < 16; ++i)
        #pragma unroll
        for (int j = 0; j < 4; ++j) o[i][j] = 0.f;
    float m0r = -INFINITY, m1r = -INFINITY, l0 = 0.f, l1 = 0.f;

    const int ntiles = (q0 + ABQ) / ABK;
    for (int t = 0; t < ntiles; ++t) {
        const int ks = t * ABK;
        __syncthreads();
        // load K (64x192) hi/lo and V (64x128) hi/lo
        for (int idx = tid; idx < ABK * 24; idx += 256) {
            int r = idx / 24, c = (idx % 24) * 8;
            cp16(sbase + B_KH + (r * KSTR + c) * 2, Kh + (size_t)(ks + r) * DH_ + c);
            cp16(sbase + B_KL + (r * KSTR + c) * 2, Kl + (size_t)(ks + r) * DH_ + c);
        }
        for (int idx = tid; idx < ABK * 16; idx += 256) {
            int r = idx >> 4, c = (idx & 15) * 8;
            cp16(sbase + B_VH + (r * VSTR + c) * 2, Vh + (size_t)(ks + r) * DV_ + c);
            cp16(sbase + B_VL + (r * VSTR + c) * 2, Vl + (size_t)(ks + r) * DV_ + c);
        }
        CP_COMMIT();
        CP_WAIT(0);
        __syncthreads();

        if (ks <= q0w + 15) {
            // ---- scores S = Qh*Kh + Ql*Kh + Qh*Kl ----
            float s[8][4];
            #pragma unroll
            for (int i = 0; i < 8; ++i)
                #pragma unroll
                for (int j = 0; j < 4; ++j) s[i][j] = 0.f;

            #pragma unroll
            for (int kst = 0; kst < 12; ++kst) {
                uint32_t qh[4], ql[4];
                uint32_t qoff = ((w * 16 + a_row) * QSTR + kst * 16 + a_kof) * 2;
                ldsm_x4(qh, sbase + B_QH + qoff);
                ldsm_x4(ql, sbase + B_QL + qoff);
                #pragma unroll
                for (int np = 0; np < 4; ++np) {
                    uint32_t kh[4], kl[4];
                    uint32_t koff = ((np * 16 + b_row) * KSTR + kst * 16 + b_kof) * 2;
                    ldsm_x4(kh, sbase + B_KH + koff);
                    ldsm_x4(kl, sbase + B_KL + koff);
                    mma16816(s[np*2+0], qh, kh[0], kh[1]);
                    mma16816(s[np*2+1], qh, kh[2], kh[3]);
                    mma16816(s[np*2+0], ql, kh[0], kh[1]);
                    mma16816(s[np*2+1], ql, kh[2], kh[3]);
                    mma16816(s[np*2+0], qh, kl[0], kl[1]);
                    mma16816(s[np*2+1], qh, kl[2], kl[3]);
                }
            }

            // ---- mask + scale + row max ----
            const int row0 = q0w + r_in;
            float tm0 = -INFINITY, tm1 = -INFINITY;
            #pragma unroll
            for (int nt = 0; nt < 8; ++nt) {
                #pragma unroll
                for (int e = 0; e < 2; ++e) {
                    int col = ks + nt * 8 + c2 + e;
                    s[nt][e]     = (col <= row0)     ? s[nt][e]     * scale : -INFINITY;
                    s[nt][e + 2] = (col <= row0 + 8) ? s[nt][e + 2] * scale : -INFINITY;
                    tm0 = fmaxf(tm0, s[nt][e]);
                    tm1 = fmaxf(tm1, s[nt][e + 2]);
                }
            }
            tm0 = fmaxf(tm0, __shfl_xor_sync(0xffffffffu, tm0, 1));
            tm0 = fmaxf(tm0, __shfl_xor_sync(0xffffffffu, tm0, 2));
            tm1 = fmaxf(tm1, __shfl_xor_sync(0xffffffffu, tm1, 1));
            tm1 = fmaxf(tm1, __shfl_xor_sync(0xffffffffu, tm1, 2));
            float mn0 = fmaxf(m0r, tm0), mn1 = fmaxf(m1r, tm1);
            float al0 = __expf(m0r - mn0), al1 = __expf(m1r - mn1);
            m0r = mn0; m1r = mn1;

            // ---- P = exp(S - m), split hi/lo, pack a-frags ----
            uint32_t pah[4][4], pal[4][4];
            float ps0 = 0.f, ps1 = 0.f;
            #pragma unroll
            for (int kc = 0; kc < 4; ++kc) {
                #pragma unroll
                for (int half = 0; half < 2; ++half) {
                    float* f = s[kc * 2 + half];
                    float p0 = __expf(f[0] - mn0), p1 = __expf(f[1] - mn0);
                    float p2 = __expf(f[2] - mn1), p3 = __expf(f[3] - mn1);
                    ps0 += p0 + p1; ps1 += p2 + p3;
                    __nv_bfloat162 h01 = __floats2bfloat162_rn(p0, p1);
                    __nv_bfloat162 h23 = __floats2bfloat162_rn(p2, p3);
                    float r0 = p0 - __bfloat162float(h01.x);
                    float r1 = p1 - __bfloat162float(h01.y);
                    float r2 = p2 - __bfloat162float(h23.x);
                    float r3 = p3 - __bfloat162float(h23.y);
                    __nv_bfloat162 l01 = __floats2bfloat162_rn(r0, r1);
                    __nv_bfloat162 l23 = __floats2bfloat162_rn(r2, r3);
                    pah[kc][half * 2 + 0] = *reinterpret_cast<uint32_t*>(&h01);
                    pah[kc][half * 2 + 1] = *reinterpret_cast<uint32_t*>(&h23);
                    pal[kc][half * 2 + 0] = *reinterpret_cast<uint32_t*>(&l01);
                    pal[kc][half * 2 + 1] = *reinterpret_cast<uint32_t*>(&l23);
                }
            }
            l0 = l0 * al0 + ps0;
            l1 = l1 * al1 + ps1;

            // ---- rescale O, then O += Ph*Vh + Pl*Vh + Ph*Vl ----
            #pragma unroll
            for (int nt = 0; nt < 16; ++nt) {
                o[nt][0] *= al0; o[nt][1] *= al0;
                o[nt][2] *= al1; o[nt][3] *= al1;
            }
            #pragma unroll
            for (int kc = 0; kc < 4; ++kc) {
                #pragma unroll
                for (int np = 0; np < 8; ++np) {
                    uint32_t vh[4], vl[4];
                    uint32_t voff = ((kc * 16 + ((grp & 1) << 3) + wi) * VSTR
                                     + np * 16 + ((grp >> 1) << 3)) * 2;
                    ldsm_x4_t(vh, sbase + B_VH + voff);
                    ldsm_x4_t(vl, sbase + B_VL + voff);
                    mma16816(o[np*2+0], pah[kc], vh[0], vh[1]);
                    mma16816(o[np*2+1], pah[kc], vh[2], vh[3]);
                    mma16816(o[np*2+0], pal[kc], vh[0], vh[1]);
                    mma16816(o[np*2+1], pal[kc], vh[2], vh[3]);
                    mma16816(o[np*2+0], pah[kc], vl[0], vl[1]);
                    mma16816(o[np*2+1], pah[kc], vl[2], vl[3]);
                }
            }
        }
    }

    // final normalize + write hi/lo bf16
    l0 += __shfl_xor_sync(0xffffffffu, l0, 1);
    l0 += __shfl_xor_sync(0xffffffffu, l0, 2);
    l1 += __shfl_xor_sync(0xffffffffu, l1, 1);
    l1 += __shfl_xor_sync(0xffffffffu, l1, 2);
    float inv0 = 1.0f / l0, inv1 = 1.0f / l1;

    const size_t row0 = (size_t)(b * SEQ + q0w + r_in) * (NH * DV_);
    const size_t row1 = row0 + 8 * (NH * DV_);
    #pragma unroll
    for (int np = 0; np < 16; ++np) {
        int col = h * DV_ + np * 8 + c2;
        float v0 = o[np][0] * inv0, v1 = o[np][1] * inv0;
        float v2 = o[np][2] * inv1, v3 = o[np][3] * inv1;
        __nv_bfloat162 h01 = __floats2bfloat162_rn(v0, v1);
        __nv_bfloat162 h23 = __floats2bfloat162_rn(v2, v3);
        __nv_bfloat162 l01 = __floats2bfloat162_rn(v0 - __bfloat162float(h01.x),
                                                   v1 - __bfloat162float(h01.y));
        __nv_bfloat162 l23 = __floats2bfloat162_rn(v2 - __bfloat162float(h23.x),
                                                   v3 - __bfloat162float(h23.y));
        *reinterpret_cast<__nv_bfloat162*>(&Ohi[row0 + col]) = h01;
        *reinterpret_cast<__nv_bfloat162*>(&Ohi[row1 + col]) = h23;
        *reinterpret_cast<__nv_bfloat162*>(&Olo[row0 + col]) = l01;
        *reinterpret_cast<__nv_bfloat162*>(&Olo[row1 + col]) = l23;
    }
}

// ----------------------------- host ----------------------------------------
extern "C" void kernel_launch(void* const* d_in, const int* in_sizes, int n_in,
                              void* d_out, int out_size)
{
    const float* X     = (const float*)d_in[0];
    const float* w_qa  = (const float*)d_in[2];
    const float* b_qa  = (const float*)d_in[3];
    const float* gq    = (const float*)d_in[4];
    const float* w_qb  = (const float*)d_in[5];
    const float* b_qb  = (const float*)d_in[6];
    const float* w_kva = (const float*)d_in[7];
    const float* b_kva = (const float*)d_in[8];
    const float* gkv   = (const float*)d_in[9];
    const float* w_kvb = (const float*)d_in[10];
    const float* b_kvb = (const float*)d_in[11];
    const float* w_o   = (const float*)d_in[12];
    const float* b_o   = (const float*)d_in[13];
    float* out = (float*)d_out;

    float *qa, *qb, *kva, *kvb;
    cudaGetSymbolAddress((void**)&qa,  g_qa);
    cudaGetSymbolAddress((void**)&qb,  g_qb);
    cudaGetSymbolAddress((void**)&kva, g_kva);
    cudaGetSymbolAddress((void**)&kvb, g_kvb);

    __nv_bfloat16 *Xhi, *Xlo, *QAhi, *QAlo, *KVAhi, *KVAlo, *AThi, *ATlo;
    __nv_bfloat16 *Qhi, *Qlo, *Khi, *Klo, *Vhi, *Vlo;
    __nv_bfloat16 *Wqah, *Wqal, *Wqbh, *Wqbl, *Wkvah, *Wkval, *Wkvbh, *Wkvbl, *Woh, *Wol;
    cudaGetSymbolAddress((void**)&Xhi,  g_Xhi);
    cudaGetSymbolAddress((void**)&Xlo,  g_Xlo);
    cudaGetSymbolAddress((void**)&QAhi, g_QAhi);
    cudaGetSymbolAddress((void**)&QAlo, g_QAlo);
    cudaGetSymbolAddress((void**)&KVAhi,g_KVAhi);
    cudaGetSymbolAddress((void**)&KVAlo,g_KVAlo);
    cudaGetSymbolAddress((void**)&AThi, g_AThi);
    cudaGetSymbolAddress((void**)&ATlo, g_ATlo);
    cudaGetSymbolAddress((void**)&Qhi,  g_Qhi);
    cudaGetSymbolAddress((void**)&Qlo,  g_Qlo);
    cudaGetSymbolAddress((void**)&Khi,  g_Khi);
    cudaGetSymbolAddress((void**)&Klo,  g_Klo);
    cudaGetSymbolAddress((void**)&Vhi,  g_Vhi);
    cudaGetSymbolAddress((void**)&Vlo,  g_Vlo);
    cudaGetSymbolAddress((void**)&Wqah, g_Wqa_hi);
    cudaGetSymbolAddress((void**)&Wqal, g_Wqa_lo);
    cudaGetSymbolAddress((void**)&Wqbh, g_Wqb_hi);
    cudaGetSymbolAddress((void**)&Wqbl, g_Wqb_lo);
    cudaGetSymbolAddress((void**)&Wkvah,g_Wkva_hi);
    cudaGetSymbolAddress((void**)&Wkval,g_Wkva_lo);
    cudaGetSymbolAddress((void**)&Wkvbh,g_Wkvb_hi);
    cudaGetSymbolAddress((void**)&Wkvbl,g_Wkvb_lo);
    cudaGetSymbolAddress((void**)&Woh,  g_Wo_hi);
    cudaGetSymbolAddress((void**)&Wol,  g_Wo_lo);

    cudaFuncSetAttribute(tc_gemm_bias,
        cudaFuncAttributeMaxDynamicSharedMemorySize, TC_SMEM_BYTES);
    cudaFuncSetAttribute(attn_mma,
        cudaFuncAttributeMaxDynamicSharedMemorySize, ATTN_SMEM);

    dim3 tpb(32, 8);

    // weight prep
    transpose_split<<<dim3(RQ_/32, DMODEL/32), tpb>>>(w_qa, DMODEL, RQ_, RQ_, Wqah, Wqal);
    transpose_split<<<dim3((NH*DH_)/32, RQ_/32), tpb>>>(w_qb, RQ_, NH*DH_, NH*DH_, Wqbh, Wqbl);
    transpose_split<<<dim3(KVAPAD/32, DMODEL/32), tpb>>>(w_kva, DMODEL, RKV_+DR_, KVAPAD, Wkvah, Wkval);
    transpose_split<<<dim3((NKV*(DN_+DV_))/32, RKV_/32), tpb>>>(w_kvb, RKV_, NKV*(DN_+DV_), NKV*(DN_+DV_), Wkvbh, Wkvbl);
    transpose_split<<<dim3(DMODEL/32, (NH*DV_)/32), tpb>>>(w_o, NH*DV_, DMODEL, DMODEL, Woh, Wol);

    // X split
    split_kernel<<<(ROWS*DMODEL + 255)/256, 256>>>(X, ROWS, DMODEL, DMODEL, Xhi, Xlo);

    // q path
    tc_gemm_bias<<<dim3(RQ_/128, ROWS/128), 256, TC_SMEM_BYTES>>>(
        ROWS, RQ_, DMODEL, Xhi, Xlo, Wqah, Wqal, b_qa, RQ_, qa, RQ_);
    rmsnorm_kernel<<<ROWS, 256>>>(qa, gq, RQ_, RQ_);
    split_kernel<<<(ROWS*RQ_ + 255)/256, 256>>>(qa, ROWS, RQ_, RQ_, QAhi, QAlo);
    tc_gemm_bias<<<dim3((NH*DH_)/128, ROWS/128), 256, TC_SMEM_BYTES>>>(
        ROWS, NH*DH_, RQ_, QAhi, QAlo, Wqbh, Wqbl, b_qb, NH*DH_, qb, NH*DH_);

    // kv path
    tc_gemm_bias<<<dim3(KVAPAD/128, ROWS/128), 256, TC_SMEM_BYTES>>>(
        ROWS, KVAPAD, DMODEL, Xhi, Xlo, Wkvah, Wkval, b_kva, RKV_+DR_, kva, KVAPAD);
    rmsnorm_kernel<<<ROWS, 256>>>(kva, gkv, RKV_, KVAPAD);
    split_kernel<<<(ROWS*RKV_ + 255)/256, 256>>>(kva, ROWS, RKV_, KVAPAD, KVAhi, KVAlo);
    tc_gemm_bias<<<dim3((NKV*(DN_+DV_))/128, ROWS/128), 256, TC_SMEM_BYTES>>>(
        ROWS, NKV*(DN_+DV_), RKV_, KVAhi, KVAlo, Wkvbh, Wkvbl, b_kvb, NKV*(DN_+DV_), kvb, NKV*(DN_+DV_));

    // rope + layout (bf16 split outputs)
    {
        int n1 = Bsz*NH*SEQ*DH_;
        rope_q_split<<<(n1 + 255)/256, 256>>>(qb, Qhi, Qlo);
        int n2 = Bsz*NKV*SEQ*(DH_+DV_);
        build_kv_split<<<(n2 + 255)/256, 256>>>(kva, kvb, Khi, Klo, Vhi, Vlo);
    }

    // attention (tensor-core, writes split output directly)
    attn_mma<<<dim3(SEQ/ABQ, NH, Bsz), 256, ATTN_SMEM>>>(
        Qhi, Qlo, Khi, Klo, Vhi, Vlo, AThi, ATlo);

    // out projection
    tc_gemm_bias<<<dim3(DMODEL/128, ROWS/128), 256, TC_SMEM_BYTES>>>(
        ROWS, DMODEL, NH*DV_, AThi, ATlo, Woh, Wol, b_o, DMODEL, out, DMODEL);
}